// round 2
// baseline (speedup 1.0000x reference)
#include <cuda_runtime.h>
#include <mma.h>
#include <math.h>

using namespace nvcuda;

#define TOTPTS 16384
#define MROWS  131072   // TOT*NV
#define KDIM   2048
#define NDIM   512

// Static device scratch (no runtime allocation allowed).
__device__ float g_H[(size_t)MROWS * NDIM];   // elu(X@W0+b0), 268MB
__device__ float g_B32[(size_t)MROWS * 32];   // bott after if1 + dirfeat, 16MB

__device__ __forceinline__ float eluf(float x) { return x > 0.f ? x : expm1f(x); }
__device__ __forceinline__ float sigm(float x) { return 1.f / (1.f + expf(-x)); }
__device__ __forceinline__ float wrsum(float v) {
#pragma unroll
    for (int o = 16; o > 0; o >>= 1) v += __shfl_xor_sync(0xffffffffu, v, o);
    return v;
}

// ---------------------------------------------------------------------------
// GEMM1: H[131072,512] = elu(X[131072,2048] @ W0[2048,512] + b0)
// wmma 3xTF32 (hi/lo split for fp32-class accuracy), block tile 128x64,
// K-step 32, 8 warps (4x2), warp tile 32x32.
// ---------------------------------------------------------------------------
__global__ void __launch_bounds__(256) gemm1_kernel(
    const float* __restrict__ X, const float* __restrict__ W,
    const float* __restrict__ bias)
{
    __shared__ float As[128 * 36];      // 128 x 32 (+4 pad)
    __shared__ float Bs[32 * 72];       // 32 x 64 (+8 pad)
    __shared__ float Cs[8 * 16 * 20];   // per-warp epilogue buffer 16x16 (ld 20)

    const int tid = threadIdx.x, wid = tid >> 5, lane = tid & 31;
    const int m0 = blockIdx.y * 128, n0 = blockIdx.x * 64;
    const int wm = (wid >> 1) * 32, wn = (wid & 1) * 32;

    wmma::fragment<wmma::accumulator, 16, 16, 8, float> acc[2][2];
#pragma unroll
    for (int i = 0; i < 2; i++)
#pragma unroll
        for (int j = 0; j < 2; j++) wmma::fill_fragment(acc[i][j], 0.f);

    for (int k0 = 0; k0 < KDIM; k0 += 32) {
#pragma unroll
        for (int i = tid; i < 1024; i += 256) {   // A tile: 128x32 as float4
            int r = i >> 3, c = (i & 7) * 4;
            float4 v = *(const float4*)(X + (size_t)(m0 + r) * KDIM + k0 + c);
            float* d = &As[r * 36 + c];
            d[0] = v.x; d[1] = v.y; d[2] = v.z; d[3] = v.w;
        }
#pragma unroll
        for (int i = tid; i < 512; i += 256) {    // B tile: 32x64 as float4
            int r = i >> 4, c = (i & 15) * 4;
            float4 v = *(const float4*)(W + (size_t)(k0 + r) * NDIM + n0 + c);
            float* d = &Bs[r * 72 + c];
            d[0] = v.x; d[1] = v.y; d[2] = v.z; d[3] = v.w;
        }
        __syncthreads();
#pragma unroll
        for (int kk = 0; kk < 4; kk++) {
            wmma::fragment<wmma::matrix_a, 16, 16, 8, wmma::precision::tf32, wmma::row_major> ah[2], al[2];
            wmma::fragment<wmma::matrix_b, 16, 16, 8, wmma::precision::tf32, wmma::row_major> bh[2], bl[2];
            wmma::load_matrix_sync(ah[0], &As[wm * 36 + kk * 8], 36);
            wmma::load_matrix_sync(ah[1], &As[(wm + 16) * 36 + kk * 8], 36);
            wmma::load_matrix_sync(bh[0], &Bs[kk * 8 * 72 + wn], 72);
            wmma::load_matrix_sync(bh[1], &Bs[kk * 8 * 72 + wn + 16], 72);
#pragma unroll
            for (int p = 0; p < 2; p++) {
#pragma unroll
                for (int t = 0; t < ah[p].num_elements; t++) {
                    float v  = ah[p].x[t];
                    float hi = wmma::__float_to_tf32(v);
                    ah[p].x[t] = hi;
                    al[p].x[t] = wmma::__float_to_tf32(v - hi);
                }
#pragma unroll
                for (int t = 0; t < bh[p].num_elements; t++) {
                    float v  = bh[p].x[t];
                    float hi = wmma::__float_to_tf32(v);
                    bh[p].x[t] = hi;
                    bl[p].x[t] = wmma::__float_to_tf32(v - hi);
                }
            }
#pragma unroll
            for (int i = 0; i < 2; i++)
#pragma unroll
                for (int j = 0; j < 2; j++) {
                    wmma::mma_sync(acc[i][j], ah[i], bl[j], acc[i][j]);
                    wmma::mma_sync(acc[i][j], al[i], bh[j], acc[i][j]);
                    wmma::mma_sync(acc[i][j], ah[i], bh[j], acc[i][j]);
                }
        }
        __syncthreads();
    }

    float* epi = &Cs[wid * 320];
#pragma unroll
    for (int i = 0; i < 2; i++)
#pragma unroll
        for (int j = 0; j < 2; j++) {
            wmma::store_matrix_sync(epi, acc[i][j], 20, wmma::mem_row_major);
            __syncwarp();
            int rb = m0 + wm + i * 16, cb = n0 + wn + j * 16;
#pragma unroll
            for (int e = lane; e < 256; e += 32) {
                int rr = e >> 4, cc = e & 15;
                float v = epi[rr * 20 + cc] + bias[cb + cc];
                g_H[(size_t)(rb + rr) * NDIM + cb + cc] = v > 0.f ? v : expm1f(v);
            }
            __syncwarp();
        }
}

// ---------------------------------------------------------------------------
// GEMM2: B32[r,:] = H[r,:] @ W1[512,32] + b1 + elu(rd-MLP(ray_diff[r]))
// warp per row, lane per output column; rd-MLP fused via shuffles.
// ---------------------------------------------------------------------------
__global__ void __launch_bounds__(256) gemm2_kernel(
    const float* __restrict__ W1, const float* __restrict__ b1,
    const float* __restrict__ rdiff,
    const float* __restrict__ rd0w, const float* __restrict__ rd0b,
    const float* __restrict__ rd1w, const float* __restrict__ rd1b)
{
    extern __shared__ float W1s[];    // 512*32 floats = 64KB
    const int tid = threadIdx.x, wid = tid >> 5, lane = tid & 31;
    for (int i = tid; i < 512 * 32 / 4; i += 256)
        ((float4*)W1s)[i] = ((const float4*)W1)[i];
    __syncthreads();

    size_t r = (size_t)blockIdx.x * 8 + wid;

    // direction feature: 4 -> 16 (elu) -> 32 (elu)
    const float* rp = rdiff + r * 4;
    float rv = (lane < 4) ? rp[lane] : 0.f;
    float r0 = __shfl_sync(0xffffffffu, rv, 0), r1 = __shfl_sync(0xffffffffu, rv, 1);
    float r2 = __shfl_sync(0xffffffffu, rv, 2), r3 = __shfl_sync(0xffffffffu, rv, 3);
    float h = 0.f;
    if (lane < 16) {
        h = rd0b[lane] + r0 * rd0w[lane] + r1 * rd0w[16 + lane]
                       + r2 * rd0w[32 + lane] + r3 * rd0w[48 + lane];
        h = eluf(h);
    }
    float d = rd1b[lane];
#pragma unroll
    for (int k = 0; k < 16; k++)
        d += __shfl_sync(0xffffffffu, h, k) * rd1w[k * 32 + lane];
    d = eluf(d);

    // H-row @ W1
    const float* hr = g_H + r * NDIM;
    float acc = 0.f;
    for (int k0 = 0; k0 < NDIM; k0 += 32) {
        float hv = hr[k0 + lane];
#pragma unroll
        for (int kk = 0; kk < 32; kk++)
            acc += __shfl_sync(0xffffffffu, hv, kk) * W1s[(k0 + kk) * 32 + lane];
    }
    g_B32[r * 32 + lane] = acc + b1[lane] + d;
}

// ---------------------------------------------------------------------------
// STAGE2: everything after if1 — per point (reductions only over NV=8 views).
// warp per point, 8 points per block, small weights staged in shared.
// ---------------------------------------------------------------------------
struct WPtrs { const float* p[20]; };

#define WTOT   19432   // weight floats (19427 padded)
#define WARPTMP 928

__global__ void __launch_bounds__(256) stage2_kernel(
    const float* __restrict__ tokG, const void* __restrict__ invG,
    WPtrs wp, float* __restrict__ out)
{
    extern __shared__ float sm[];
    const int tid = threadIdx.x, wid = tid >> 5, lane = tid & 31;

    const int cnt[20] = {128,8,8,1,11264,64,2048,32,1024,32,1056,33,1024,32,32,1,2080,32,512,16};
    const int off[20] = {0,128,136,144,145,11409,11473,13521,13553,14577,14609,15665,15698,16722,16754,16786,16787,18867,18899,19411};
    for (int s = 0; s < 20; s++) {
        const float* src = wp.p[s]; float* dst = sm + off[s];
        for (int i = tid; i < cnt[s]; i += 256) dst[i] = src[i];
    }
    __syncthreads();

    const float* nr0w = sm;          const float* nr0b = sm + 128;
    const float* nr1w = sm + 136;    const float* nr1b = sm + 144;
    const float* bf0w = sm + 145;    const float* bf0b = sm + 11409;
    const float* bf1w = sm + 11473;  const float* bf1b = sm + 13521;
    const float* vf0w = sm + 13553;  const float* vf0b = sm + 14577;
    const float* vf1w = sm + 14609;  const float* vf1b = sm + 15665;
    const float* v20w = sm + 15698;  const float* v20b = sm + 16722;
    const float* v21w = sm + 16754;  const float* v21b = sm + 16786;
    const float* gf0w = sm + 16787;  const float* gf0b = sm + 18867;
    const float* gf1w = sm + 18899;  const float* gf1b = sm + 19411;

    float* T = sm + WTOT + wid * WARPTMP;
    float* tokW = T;        float* bottW = T + 128;  float* xW  = T + 384;
    float* gfW  = T + 640;  float* h64W  = T + 768;  float* h33W = T + 832;
    float* wtW  = T + 872;  float* w0W   = T + 880;  float* mskW = T + 888;
    float* visW = T + 896;  float* w2W   = T + 904;

    int t = blockIdx.x * 8 + wid;

    // -------- dtype-robust invalid_features read ---------------------------
    // bool may be delivered as uint8, int32, or float32. For int32/float32,
    // (uint32 bits != 0) is the right predicate; only uint8 changes stride.
    // Detect uint8 layout: a byte == 1 at an offset not divisible by 4 can
    // only occur in the uint8 layout (int32 -> 0x00 there, f32 -> 0x80/0x3F).
    const unsigned char* bb = (const unsigned char*)invG;
    int u8f = 0;
    for (int i = lane; i < 256; i += 32) if ((i & 3) && bb[i] == 1) u8f = 1;
    u8f = (__ballot_sync(0xffffffffu, u8f) != 0);

    for (int i = lane; i < 128; i += 32) tokW[i]  = tokG[(size_t)t * 128 + i];
    for (int i = lane; i < 256; i += 32) bottW[i] = g_B32[(size_t)t * 256 + i];
    float mv = 0.f;
    if (lane < 8) {
        int idx = t * 8 + lane;
        bool inv = u8f ? (bb[idx] != 0)
                       : (((const unsigned int*)invG)[idx] != 0u);
        mv = inv ? 0.f : 1.f;
    }
    float msum = wrsum(mv);
    if (lane < 8) { mskW[lane] = mv; wtW[lane] = mv / (msum + 1e-8f); }
    __syncwarp();

    // nr: 16 -> 8 (elu) -> 1, sigmoid, * weight  (lane v < 8 handles a view)
    if (lane < 8) {
        float hh[8];
#pragma unroll
        for (int i = 0; i < 8; i++) hh[i] = nr0b[i];
#pragma unroll
        for (int k = 0; k < 16; k++) {
            float tv = tokW[lane * 16 + k];
#pragma unroll
            for (int i = 0; i < 8; i++) hh[i] += tv * nr0w[k * 8 + i];
        }
        float s = nr1b[0];
#pragma unroll
        for (int i = 0; i < 8; i++) s += eluf(hh[i]) * nr1w[i];
        w0W[lane] = sigm(s) * wtW[lane];
    }
    __syncwarp();

    // weighted mean/var of bott (weight0 and weight)
    {
        float m0 = 0.f, m1 = 0.f;
#pragma unroll
        for (int v = 0; v < 8; v++) { float b = bottW[v * 32 + lane]; m0 += b * w0W[v]; m1 += b * wtW[v]; }
        float v0 = 0.f, v1 = 0.f;
#pragma unroll
        for (int v = 0; v < 8; v++) {
            float b = bottW[v * 32 + lane]; float d0 = b - m0, d1 = b - m1;
            v0 += w0W[v] * d0 * d0; v1 += wtW[v] * d1 * d1;
        }
        gfW[lane] = m0; gfW[32 + lane] = v0; gfW[64 + lane] = m1; gfW[96 + lane] = v1;
    }
    __syncwarp();

    for (int v = 0; v < 8; v++) {
        // bf0: 176 -> 64 (elu)
        for (int jj = lane; jj < 64; jj += 32) {
            float a = bf0b[jj];
            for (int k = 0; k < 128; k++) a += gfW[k] * bf0w[k * 64 + jj];
#pragma unroll
            for (int k = 0; k < 32; k++) a += bottW[v * 32 + k] * bf0w[(128 + k) * 64 + jj];
#pragma unroll
            for (int k = 0; k < 16; k++) a += tokW[v * 16 + k] * bf0w[(160 + k) * 64 + jj];
            h64W[jj] = eluf(a);
        }
        __syncwarp();
        // bf1: 64 -> 32 (elu) -> x
        {
            float a = bf1b[lane];
#pragma unroll
            for (int k = 0; k < 64; k++) a += h64W[k] * bf1w[k * 32 + lane];
            xW[v * 32 + lane] = eluf(a);
        }
        __syncwarp();
        // vf on x*weight: 32 -> 32 (elu) -> 33 (elu)
        float wv = wtW[v];
        {
            float a = vf0b[lane];
#pragma unroll
            for (int k = 0; k < 32; k++) a += xW[v * 32 + k] * wv * vf0w[k * 32 + lane];
            h33W[lane] = eluf(a);
        }
        __syncwarp();
        float xres;
        {
            float a = vf1b[lane];
#pragma unroll
            for (int k = 0; k < 32; k++) a += h33W[k] * vf1w[k * 33 + lane];
            xres = eluf(a);
        }
        if (lane == 0) {
            float a = vf1b[32];
#pragma unroll
            for (int k = 0; k < 32; k++) a += h33W[k] * vf1w[k * 33 + 32];
            visW[v] = sigm(eluf(a)) * mskW[v];
        }
        __syncwarp();
        xW[v * 32 + lane] += xres;   // x = x + x_res
        __syncwarp();
        // v2 on x*vis: 32 -> 32 (elu) -> 1, sigmoid * mask
        float vv = visW[v];
        {
            float a = v20b[lane];
#pragma unroll
            for (int k = 0; k < 32; k++) a += xW[v * 32 + k] * vv * v20w[k * 32 + lane];
            h33W[lane] = eluf(a);
        }
        __syncwarp();
        {
            float p = h33W[lane] * v21w[lane];
            float s = wrsum(p) + v21b[0];
            if (lane == 0) w2W[v] = sigm(s) * mskW[v];
        }
        __syncwarp();
    }

    // weight2 = vis / (sum + 1e-8); wbar = mean over views
    {
        float vv = (lane < 8) ? w2W[lane] : 0.f;
        float s = wrsum(vv);
        if (lane < 8) w2W[lane] = vv / (s + 1e-8f);
    }
    __syncwarp();
    float wbar;
    {
        float vv = (lane < 8) ? w2W[lane] : 0.f;
        wbar = wrsum(vv) * 0.125f;
    }
    // weighted mean/var of x
    {
        float m = 0.f;
#pragma unroll
        for (int v = 0; v < 8; v++) m += xW[v * 32 + lane] * w2W[v];
        float va = 0.f;
#pragma unroll
        for (int v = 0; v < 8; v++) { float dd = xW[v * 32 + lane] - m; va += w2W[v] * dd * dd; }
        gfW[lane] = m; gfW[32 + lane] = va;
        if (lane == 0) gfW[64] = wbar;
    }
    __syncwarp();
    // gf: 65 -> 32 (elu) -> 16 (elu)
    {
        float a = gf0b[lane];
#pragma unroll
        for (int k = 0; k < 65; k++) a += gfW[k] * gf0w[k * 32 + lane];
        h33W[lane] = eluf(a);
    }
    __syncwarp();
    if (lane < 16) {
        float a = gf1b[lane];
#pragma unroll
        for (int k = 0; k < 32; k++) a += h33W[k] * gf1w[k * 16 + lane];
        out[(size_t)t * 16 + lane] = eluf(a);
    }
}

// ---------------------------------------------------------------------------
extern "C" void kernel_launch(void* const* d_in, const int* in_sizes, int n_in,
                              void* d_out, int out_size)
{
    const float* tok   = (const float*)d_in[0];
    const float* bott  = (const float*)d_in[1];
    const float* rdiff = (const float*)d_in[2];
    const void*  inval = (const void*)d_in[3];
    const float* rd0w = (const float*)d_in[4];  const float* rd0b = (const float*)d_in[5];
    const float* rd1w = (const float*)d_in[6];  const float* rd1b = (const float*)d_in[7];
    const float* if0w = (const float*)d_in[8];  const float* if0b = (const float*)d_in[9];
    const float* if1w = (const float*)d_in[10]; const float* if1b = (const float*)d_in[11];
    float* out = (float*)d_out;

    WPtrs wp;
    for (int i = 0; i < 20; i++) wp.p[i] = (const float*)d_in[12 + i];

    const int stage2_smem = (WTOT + 8 * WARPTMP) * 4;   // ~107.4 KB
    cudaFuncSetAttribute(gemm2_kernel, cudaFuncAttributeMaxDynamicSharedMemorySize, 65536);
    cudaFuncSetAttribute(stage2_kernel, cudaFuncAttributeMaxDynamicSharedMemorySize, stage2_smem);

    gemm1_kernel<<<dim3(8, 1024), 256>>>(bott, if0w, if0b);
    gemm2_kernel<<<MROWS / 8, 256, 65536>>>(if1w, if1b, rdiff, rd0w, rd0b, rd1w, rd1b);
    stage2_kernel<<<TOTPTS / 8, 256, stage2_smem>>>(tok, inval, wp, out);
}

// round 3
// speedup vs baseline: 2.1091x; 2.1091x over previous
#include <cuda_runtime.h>
#include <mma.h>
#include <math.h>

using namespace nvcuda;

#define TOTPTS 16384
#define MROWS  131072   // TOT*NV
#define KDIM   2048
#define NDIM   512

// Static device scratch (no runtime allocation allowed).
__device__ float g_part[(size_t)8 * MROWS * 32];  // per-N-chunk partial B32, 128MB
__device__ float g_B32[(size_t)MROWS * 32];       // bott after if1 + dirfeat, 16MB

__device__ __forceinline__ float eluf(float x) { return x > 0.f ? x : expm1f(x); }
__device__ __forceinline__ float sigm(float x) { return 1.f / (1.f + expf(-x)); }
__device__ __forceinline__ float wrsum(float v) {
#pragma unroll
    for (int o = 16; o > 0; o >>= 1) v += __shfl_xor_sync(0xffffffffu, v, o);
    return v;
}

__device__ __forceinline__ void cp16(void* smem_dst, const void* gmem_src) {
    unsigned int s = (unsigned int)__cvta_generic_to_shared(smem_dst);
    asm volatile("cp.async.cg.shared.global [%0], [%1], 16;\n" :: "r"(s), "l"(gmem_src));
}
__device__ __forceinline__ void cp_commit() { asm volatile("cp.async.commit_group;\n"); }
template <int N>
__device__ __forceinline__ void cp_wait() { asm volatile("cp.async.wait_group %0;\n" :: "n"(N)); }

// ---------------------------------------------------------------------------
// GEMM1 fused: per block computes Htile = elu(X[128,2048] @ W0[:,n0:n0+64] + b0)
// then partial B32 = Htile @ W1[n0:n0+64,:] written to g_part[nchunk].
// wmma 1xTF32, 2-stage cp.async pipeline, block tile 128x64, 8 warps.
// ---------------------------------------------------------------------------
#define OFF_W1S 0          // 64 x 36       (2304 floats)
#define OFF_AS  2304       // 2 x 128 x 36  (9216 floats)  [epilogue Hs aliases here]
#define OFF_BS  11520      // 2 x 32 x 72   (4608 floats)
#define SMEM_G1 ((16128) * 4)

__global__ void __launch_bounds__(256) gemm1_kernel(
    const float* __restrict__ X, const float* __restrict__ W0,
    const float* __restrict__ b0, const float* __restrict__ W1)
{
    extern __shared__ float sm[];
    float* W1s = sm + OFF_W1S;
    float* As  = sm + OFF_AS;
    float* Bs  = sm + OFF_BS;

    const int tid = threadIdx.x, wid = tid >> 5, lane = tid & 31;
    const int p = blockIdx.x;                 // N-chunk 0..7
    const int m0 = blockIdx.y * 128, n0 = p * 64;
    const int wm = (wid >> 1) * 32, wn = (wid & 1) * 32;

    // W1 chunk -> smem (tf32-rounded once)
    for (int i = tid; i < 64 * 32; i += 256) {
        int r = i >> 5, c = i & 31;
        W1s[r * 36 + c] = wmma::__float_to_tf32(W1[(size_t)(n0 + r) * 32 + c]);
    }

    wmma::fragment<wmma::accumulator, 16, 16, 8, float> acc[2][2];
#pragma unroll
    for (int i = 0; i < 2; i++)
#pragma unroll
        for (int j = 0; j < 2; j++) wmma::fill_fragment(acc[i][j], 0.f);

    // prologue: stage 0
    {
#pragma unroll
        for (int i = tid; i < 1024; i += 256) {
            int r = i >> 3, c = (i & 7) * 4;
            cp16(&As[r * 36 + c], X + (size_t)(m0 + r) * KDIM + c);
        }
#pragma unroll
        for (int i = tid; i < 512; i += 256) {
            int r = i >> 4, c = (i & 15) * 4;
            cp16(&Bs[r * 72 + c], W0 + (size_t)r * NDIM + n0 + c);
        }
        cp_commit();
    }

    for (int t = 0; t < 64; t++) {
        int nt = t + 1;
        if (nt < 64) {
            int st = nt & 1, k0 = nt * 32;
#pragma unroll
            for (int i = tid; i < 1024; i += 256) {
                int r = i >> 3, c = (i & 7) * 4;
                cp16(&As[st * 4608 + r * 36 + c], X + (size_t)(m0 + r) * KDIM + k0 + c);
            }
#pragma unroll
            for (int i = tid; i < 512; i += 256) {
                int r = i >> 4, c = (i & 15) * 4;
                cp16(&Bs[st * 2304 + r * 72 + c], W0 + (size_t)(k0 + r) * NDIM + n0 + c);
            }
        }
        cp_commit();
        cp_wait<1>();
        __syncthreads();

        const float* A = As + (t & 1) * 4608;
        const float* B = Bs + (t & 1) * 2304;
#pragma unroll
        for (int kk = 0; kk < 4; kk++) {
            wmma::fragment<wmma::matrix_a, 16, 16, 8, wmma::precision::tf32, wmma::row_major> a0, a1;
            wmma::fragment<wmma::matrix_b, 16, 16, 8, wmma::precision::tf32, wmma::row_major> b0f, b1f;
            wmma::load_matrix_sync(a0, &A[wm * 36 + kk * 8], 36);
            wmma::load_matrix_sync(a1, &A[(wm + 16) * 36 + kk * 8], 36);
            wmma::load_matrix_sync(b0f, &B[kk * 8 * 72 + wn], 72);
            wmma::load_matrix_sync(b1f, &B[kk * 8 * 72 + wn + 16], 72);
#pragma unroll
            for (int e = 0; e < a0.num_elements; e++) {
                a0.x[e] = wmma::__float_to_tf32(a0.x[e]);
                a1.x[e] = wmma::__float_to_tf32(a1.x[e]);
            }
#pragma unroll
            for (int e = 0; e < b0f.num_elements; e++) {
                b0f.x[e] = wmma::__float_to_tf32(b0f.x[e]);
                b1f.x[e] = wmma::__float_to_tf32(b1f.x[e]);
            }
            wmma::mma_sync(acc[0][0], a0, b0f, acc[0][0]);
            wmma::mma_sync(acc[0][1], a0, b1f, acc[0][1]);
            wmma::mma_sync(acc[1][0], a1, b0f, acc[1][0]);
            wmma::mma_sync(acc[1][1], a1, b1f, acc[1][1]);
        }
        __syncthreads();
    }

    // ---- epilogue: Hs = tf32(elu(acc + b0)), then partial B32 = Hs @ W1s ----
    float* Hs = As;   // 128 x 68 (8704 floats <= 9216)
#pragma unroll
    for (int i = 0; i < 2; i++)
#pragma unroll
        for (int j = 0; j < 2; j++)
            wmma::store_matrix_sync(&Hs[(wm + i * 16) * 68 + wn + j * 16], acc[i][j], 68,
                                    wmma::mem_row_major);
    __syncthreads();

    {
        float bc = b0[n0 + (tid & 63)];
#pragma unroll
        for (int idx = tid; idx < 128 * 64; idx += 256) {
            int r = idx >> 6, c = idx & 63;
            float v = Hs[r * 68 + c] + bc;
            Hs[r * 68 + c] = wmma::__float_to_tf32(eluf(v));
        }
    }
    __syncthreads();

    {
        int r0 = wid * 16;
        wmma::fragment<wmma::accumulator, 16, 16, 8, float> oacc[2];
        wmma::fill_fragment(oacc[0], 0.f);
        wmma::fill_fragment(oacc[1], 0.f);
#pragma unroll
        for (int kk = 0; kk < 8; kk++) {
            wmma::fragment<wmma::matrix_a, 16, 16, 8, wmma::precision::tf32, wmma::row_major> af;
            wmma::fragment<wmma::matrix_b, 16, 16, 8, wmma::precision::tf32, wmma::row_major> bf0, bf1;
            wmma::load_matrix_sync(af, &Hs[r0 * 68 + kk * 8], 68);
            wmma::load_matrix_sync(bf0, &W1s[kk * 8 * 36], 36);
            wmma::load_matrix_sync(bf1, &W1s[kk * 8 * 36 + 16], 36);
            wmma::mma_sync(oacc[0], af, bf0, oacc[0]);
            wmma::mma_sync(oacc[1], af, bf1, oacc[1]);
        }
        float* dst = g_part + (size_t)p * MROWS * 32 + (size_t)(m0 + r0) * 32;
        wmma::store_matrix_sync(dst, oacc[0], 32, wmma::mem_row_major);
        wmma::store_matrix_sync(dst + 16, oacc[1], 32, wmma::mem_row_major);
    }
}

// ---------------------------------------------------------------------------
// COMBINE: B32[r,:] = sum_p part[p][r,:] + b1 + elu(rd-MLP(ray_diff[r]))
// warp per row.
// ---------------------------------------------------------------------------
__global__ void __launch_bounds__(256) combine_kernel(
    const float* __restrict__ b1, const float* __restrict__ rdiff,
    const float* __restrict__ rd0w, const float* __restrict__ rd0b,
    const float* __restrict__ rd1w, const float* __restrict__ rd1b)
{
    const int tid = threadIdx.x, wid = tid >> 5, lane = tid & 31;
    size_t r = (size_t)blockIdx.x * 8 + wid;

    // direction feature: 4 -> 16 (elu) -> 32 (elu)
    const float* rp = rdiff + r * 4;
    float rv = (lane < 4) ? rp[lane] : 0.f;
    float r0 = __shfl_sync(0xffffffffu, rv, 0), r1 = __shfl_sync(0xffffffffu, rv, 1);
    float r2 = __shfl_sync(0xffffffffu, rv, 2), r3 = __shfl_sync(0xffffffffu, rv, 3);
    float h = 0.f;
    if (lane < 16) {
        h = rd0b[lane] + r0 * rd0w[lane] + r1 * rd0w[16 + lane]
                       + r2 * rd0w[32 + lane] + r3 * rd0w[48 + lane];
        h = eluf(h);
    }
    float d = rd1b[lane];
#pragma unroll
    for (int k = 0; k < 16; k++)
        d += __shfl_sync(0xffffffffu, h, k) * rd1w[k * 32 + lane];
    d = eluf(d);

    float s = b1[lane] + d;
#pragma unroll
    for (int p = 0; p < 8; p++)
        s += g_part[(size_t)p * MROWS * 32 + r * 32 + lane];
    g_B32[r * 32 + lane] = s;
}

// ---------------------------------------------------------------------------
// STAGE2: everything after if1 — per point (reductions only over NV=8 views).
// warp per point, 8 points per block, small weights staged in shared.
// ---------------------------------------------------------------------------
struct WPtrs { const float* p[20]; };

#define WTOT   19432   // weight floats (19427 padded)
#define WARPTMP 928

__global__ void __launch_bounds__(256) stage2_kernel(
    const float* __restrict__ tokG, const void* __restrict__ invG,
    WPtrs wp, float* __restrict__ out)
{
    extern __shared__ float sm[];
    const int tid = threadIdx.x, wid = tid >> 5, lane = tid & 31;

    const int cnt[20] = {128,8,8,1,11264,64,2048,32,1024,32,1056,33,1024,32,32,1,2080,32,512,16};
    const int off[20] = {0,128,136,144,145,11409,11473,13521,13553,14577,14609,15665,15698,16722,16754,16786,16787,18867,18899,19411};
    for (int s = 0; s < 20; s++) {
        const float* src = wp.p[s]; float* dst = sm + off[s];
        for (int i = tid; i < cnt[s]; i += 256) dst[i] = src[i];
    }
    __syncthreads();

    const float* nr0w = sm;          const float* nr0b = sm + 128;
    const float* nr1w = sm + 136;    const float* nr1b = sm + 144;
    const float* bf0w = sm + 145;    const float* bf0b = sm + 11409;
    const float* bf1w = sm + 11473;  const float* bf1b = sm + 13521;
    const float* vf0w = sm + 13553;  const float* vf0b = sm + 14577;
    const float* vf1w = sm + 14609;  const float* vf1b = sm + 15665;
    const float* v20w = sm + 15698;  const float* v20b = sm + 16722;
    const float* v21w = sm + 16754;  const float* v21b = sm + 16786;
    const float* gf0w = sm + 16787;  const float* gf0b = sm + 18867;
    const float* gf1w = sm + 18899;  const float* gf1b = sm + 19411;

    float* T = sm + WTOT + wid * WARPTMP;
    float* tokW = T;        float* bottW = T + 128;  float* xW  = T + 384;
    float* gfW  = T + 640;  float* h64W  = T + 768;  float* h33W = T + 832;
    float* wtW  = T + 872;  float* w0W   = T + 880;  float* mskW = T + 888;
    float* visW = T + 896;  float* w2W   = T + 904;

    int t = blockIdx.x * 8 + wid;

    // dtype-robust invalid_features read (uint8 vs 4-byte encodings)
    const unsigned char* bb = (const unsigned char*)invG;
    int u8f = 0;
    for (int i = lane; i < 256; i += 32) if ((i & 3) && bb[i] == 1) u8f = 1;
    u8f = (__ballot_sync(0xffffffffu, u8f) != 0);

    for (int i = lane; i < 128; i += 32) tokW[i]  = tokG[(size_t)t * 128 + i];
    for (int i = lane; i < 256; i += 32) bottW[i] = g_B32[(size_t)t * 256 + i];
    float mv = 0.f;
    if (lane < 8) {
        int idx = t * 8 + lane;
        bool inv = u8f ? (bb[idx] != 0)
                       : (((const unsigned int*)invG)[idx] != 0u);
        mv = inv ? 0.f : 1.f;
    }
    float msum = wrsum(mv);
    if (lane < 8) { mskW[lane] = mv; wtW[lane] = mv / (msum + 1e-8f); }
    __syncwarp();

    // nr: 16 -> 8 (elu) -> 1, sigmoid, * weight
    if (lane < 8) {
        float hh[8];
#pragma unroll
        for (int i = 0; i < 8; i++) hh[i] = nr0b[i];
#pragma unroll
        for (int k = 0; k < 16; k++) {
            float tv = tokW[lane * 16 + k];
#pragma unroll
            for (int i = 0; i < 8; i++) hh[i] += tv * nr0w[k * 8 + i];
        }
        float s = nr1b[0];
#pragma unroll
        for (int i = 0; i < 8; i++) s += eluf(hh[i]) * nr1w[i];
        w0W[lane] = sigm(s) * wtW[lane];
    }
    __syncwarp();

    // weighted mean/var of bott (weight0 and weight)
    {
        float m0 = 0.f, m1 = 0.f;
#pragma unroll
        for (int v = 0; v < 8; v++) { float b = bottW[v * 32 + lane]; m0 += b * w0W[v]; m1 += b * wtW[v]; }
        float v0 = 0.f, v1 = 0.f;
#pragma unroll
        for (int v = 0; v < 8; v++) {
            float b = bottW[v * 32 + lane]; float d0 = b - m0, d1 = b - m1;
            v0 += w0W[v] * d0 * d0; v1 += wtW[v] * d1 * d1;
        }
        gfW[lane] = m0; gfW[32 + lane] = v0; gfW[64 + lane] = m1; gfW[96 + lane] = v1;
    }
    __syncwarp();

    for (int v = 0; v < 8; v++) {
        // bf0: 176 -> 64 (elu)
        for (int jj = lane; jj < 64; jj += 32) {
            float a = bf0b[jj];
            for (int k = 0; k < 128; k++) a += gfW[k] * bf0w[k * 64 + jj];
#pragma unroll
            for (int k = 0; k < 32; k++) a += bottW[v * 32 + k] * bf0w[(128 + k) * 64 + jj];
#pragma unroll
            for (int k = 0; k < 16; k++) a += tokW[v * 16 + k] * bf0w[(160 + k) * 64 + jj];
            h64W[jj] = eluf(a);
        }
        __syncwarp();
        // bf1: 64 -> 32 (elu) -> x
        {
            float a = bf1b[lane];
#pragma unroll
            for (int k = 0; k < 64; k++) a += h64W[k] * bf1w[k * 32 + lane];
            xW[v * 32 + lane] = eluf(a);
        }
        __syncwarp();
        // vf on x*weight: 32 -> 32 (elu) -> 33 (elu)
        float wv = wtW[v];
        {
            float a = vf0b[lane];
#pragma unroll
            for (int k = 0; k < 32; k++) a += xW[v * 32 + k] * wv * vf0w[k * 32 + lane];
            h33W[lane] = eluf(a);
        }
        __syncwarp();
        float xres;
        {
            float a = vf1b[lane];
#pragma unroll
            for (int k = 0; k < 32; k++) a += h33W[k] * vf1w[k * 33 + lane];
            xres = eluf(a);
        }
        if (lane == 0) {
            float a = vf1b[32];
#pragma unroll
            for (int k = 0; k < 32; k++) a += h33W[k] * vf1w[k * 33 + 32];
            visW[v] = sigm(eluf(a)) * mskW[v];
        }
        __syncwarp();
        xW[v * 32 + lane] += xres;   // x = x + x_res
        __syncwarp();
        // v2 on x*vis: 32 -> 32 (elu) -> 1, sigmoid * mask
        float vv = visW[v];
        {
            float a = v20b[lane];
#pragma unroll
            for (int k = 0; k < 32; k++) a += xW[v * 32 + k] * vv * v20w[k * 32 + lane];
            h33W[lane] = eluf(a);
        }
        __syncwarp();
        {
            float p = h33W[lane] * v21w[lane];
            float s = wrsum(p) + v21b[0];
            if (lane == 0) w2W[v] = sigm(s) * mskW[v];
        }
        __syncwarp();
    }

    // weight2 = vis / (sum + 1e-8); wbar = mean over views
    {
        float vv = (lane < 8) ? w2W[lane] : 0.f;
        float s = wrsum(vv);
        if (lane < 8) w2W[lane] = vv / (s + 1e-8f);
    }
    __syncwarp();
    float wbar;
    {
        float vv = (lane < 8) ? w2W[lane] : 0.f;
        wbar = wrsum(vv) * 0.125f;
    }
    // weighted mean/var of x
    {
        float m = 0.f;
#pragma unroll
        for (int v = 0; v < 8; v++) m += xW[v * 32 + lane] * w2W[v];
        float va = 0.f;
#pragma unroll
        for (int v = 0; v < 8; v++) { float dd = xW[v * 32 + lane] - m; va += w2W[v] * dd * dd; }
        gfW[lane] = m; gfW[32 + lane] = va;
        if (lane == 0) gfW[64] = wbar;
    }
    __syncwarp();
    // gf: 65 -> 32 (elu) -> 16 (elu)
    {
        float a = gf0b[lane];
#pragma unroll
        for (int k = 0; k < 65; k++) a += gfW[k] * gf0w[k * 32 + lane];
        h33W[lane] = eluf(a);
    }
    __syncwarp();
    if (lane < 16) {
        float a = gf1b[lane];
#pragma unroll
        for (int k = 0; k < 32; k++) a += h33W[k] * gf1w[k * 16 + lane];
        out[(size_t)t * 16 + lane] = eluf(a);
    }
}

// ---------------------------------------------------------------------------
extern "C" void kernel_launch(void* const* d_in, const int* in_sizes, int n_in,
                              void* d_out, int out_size)
{
    const float* tok   = (const float*)d_in[0];
    const float* bott  = (const float*)d_in[1];
    const float* rdiff = (const float*)d_in[2];
    const void*  inval = (const void*)d_in[3];
    const float* rd0w = (const float*)d_in[4];  const float* rd0b = (const float*)d_in[5];
    const float* rd1w = (const float*)d_in[6];  const float* rd1b = (const float*)d_in[7];
    const float* if0w = (const float*)d_in[8];  const float* if0b = (const float*)d_in[9];
    const float* if1w = (const float*)d_in[10]; const float* if1b = (const float*)d_in[11];
    float* out = (float*)d_out;

    WPtrs wp;
    for (int i = 0; i < 20; i++) wp.p[i] = (const float*)d_in[12 + i];

    const int stage2_smem = (WTOT + 8 * WARPTMP) * 4;   // ~107.4 KB
    cudaFuncSetAttribute(gemm1_kernel, cudaFuncAttributeMaxDynamicSharedMemorySize, SMEM_G1);
    cudaFuncSetAttribute(stage2_kernel, cudaFuncAttributeMaxDynamicSharedMemorySize, stage2_smem);

    gemm1_kernel<<<dim3(8, 1024), 256, SMEM_G1>>>(bott, if0w, if0b, if1w);
    combine_kernel<<<MROWS / 8, 256>>>(if1b, rdiff, rd0w, rd0b, rd1w, rd1b);
    stage2_kernel<<<TOTPTS / 8, 256, stage2_smem>>>(tok, inval, wp, out);
}

// round 5
// speedup vs baseline: 2.3921x; 1.1342x over previous
#include <cuda_runtime.h>
#include <mma.h>
#include <math.h>
#include <stdint.h>

using namespace nvcuda;

#define TOTPTS 16384
#define MROWS  131072   // TOT*NV
#define KDIM   2048
#define NDIM   512

// Static device scratch (no runtime allocation allowed).
__device__ float g_part[(size_t)4 * MROWS * 32];  // per-N-chunk partial B32, 64MB
__device__ float g_B32[(size_t)MROWS * 32];       // bott after if1 + dirfeat, 16MB

__device__ __forceinline__ float eluf(float x) { return x > 0.f ? x : expm1f(x); }
__device__ __forceinline__ float sigm(float x) { return 1.f / (1.f + expf(-x)); }
__device__ __forceinline__ float wrsum(float v) {
#pragma unroll
    for (int o = 16; o > 0; o >>= 1) v += __shfl_xor_sync(0xffffffffu, v, o);
    return v;
}
__device__ __forceinline__ float rnd_tf32(float x) {
    float r;
    asm("cvt.rna.tf32.f32 %0, %1;" : "=f"(r) : "f"(x));
    return r;
}

__device__ __forceinline__ void cp16(void* smem_dst, const void* gmem_src) {
    unsigned int s = (unsigned int)__cvta_generic_to_shared(smem_dst);
    asm volatile("cp.async.cg.shared.global [%0], [%1], 16;\n" :: "r"(s), "l"(gmem_src));
}
__device__ __forceinline__ void cp_commit() { asm volatile("cp.async.commit_group;\n"); }
template <int N>
__device__ __forceinline__ void cp_wait() { asm volatile("cp.async.wait_group %0;\n" :: "n"(N)); }

// ---------------------------------------------------------------------------
// GEMM1 fused (wmma tf32, no in-fragment cvt — operands pre-rounded in smem):
// per CTA: Htile = elu(X[128,2048] @ W0[:, n0:n0+128] + b0)  (3-stage pipeline)
// then partial B32 = Htile @ W1[n0:n0+128, :] -> g_part[nchunk].
// grid (4, 1024): nchunk fastest so X tiles stay L2-resident across chunks.
// ---------------------------------------------------------------------------
#define ASTRIDE 36
#define BSTRIDE 132
#define AFLOATS (128 * ASTRIDE)   // 4608
#define BFLOATS (32 * BSTRIDE)    // 4224
#define STAGEF  (AFLOATS + BFLOATS)
#define HDRF    512
#define SMEM_G1 ((HDRF + 3 * STAGEF) * 4)   // 108032 B

__device__ __forceinline__ void load_tile(float* sm, const float* __restrict__ X,
                                          const float* __restrict__ W0,
                                          int m0, int n0, int t, int s) {
    const int k0 = t * 32;
    float* A = sm + HDRF + s * STAGEF;
    float* B = A + AFLOATS;
#pragma unroll
    for (int i = threadIdx.x; i < 1024; i += 256) {   // A: 128 x 32
        int r = i >> 3, c = (i & 7) * 4;
        cp16(&A[r * ASTRIDE + c], X + (size_t)(m0 + r) * KDIM + k0 + c);
    }
#pragma unroll
    for (int i = threadIdx.x; i < 1024; i += 256) {   // B: 32 x 128
        int r = i >> 5, c = (i & 31) * 4;
        cp16(&B[r * BSTRIDE + c], W0 + (size_t)(k0 + r) * NDIM + n0 + c);
    }
}

__global__ void __launch_bounds__(256, 2) gemm1_kernel(
    const float* __restrict__ X, const float* __restrict__ W0,
    const float* __restrict__ b0, const float* __restrict__ W1)
{
    extern __shared__ float sm[];
    const int tid = threadIdx.x, wid = tid >> 5, lane = tid & 31;
    const int p = blockIdx.x;                  // N-chunk 0..3
    const int m0 = blockIdx.y * 128, n0 = p * 128;
    const int wm = (wid >> 1) * 32, wn = (wid & 1) * 64;

    if (tid < 128) sm[tid] = b0[n0 + tid];     // b0 chunk -> header

    wmma::fragment<wmma::accumulator, 16, 16, 8, float> acc[2][4];
#pragma unroll
    for (int i = 0; i < 2; i++)
#pragma unroll
        for (int j = 0; j < 4; j++) wmma::fill_fragment(acc[i][j], 0.f);

    // prologue: stages 0,1
    load_tile(sm, X, W0, m0, n0, 0, 0); cp_commit();
    load_tile(sm, X, W0, m0, n0, 1, 1); cp_commit();

    for (int t = 0; t < 64; t++) {
        const int s = t % 3;
        if (t < 62) { cp_wait<1>(); } else { cp_wait<0>(); }
        __syncthreads();

        float* A = sm + HDRF + s * STAGEF;
        float* B = A + AFLOATS;

        // RN-round both tiles to tf32 in-place (so fragment loads need no cvt)
#pragma unroll
        for (int i = tid; i < 1024; i += 256) {
            int r = i >> 3, c = (i & 7) * 4;
            float4* pa = reinterpret_cast<float4*>(&A[r * ASTRIDE + c]);
            float4 v = *pa;
            v.x = rnd_tf32(v.x); v.y = rnd_tf32(v.y);
            v.z = rnd_tf32(v.z); v.w = rnd_tf32(v.w);
            *pa = v;
        }
#pragma unroll
        for (int i = tid; i < 1024; i += 256) {
            int r = i >> 5, c = (i & 31) * 4;
            float4* pb = reinterpret_cast<float4*>(&B[r * BSTRIDE + c]);
            float4 v = *pb;
            v.x = rnd_tf32(v.x); v.y = rnd_tf32(v.y);
            v.z = rnd_tf32(v.z); v.w = rnd_tf32(v.w);
            *pb = v;
        }
        __syncthreads();

#pragma unroll
        for (int kk = 0; kk < 4; kk++) {
            wmma::fragment<wmma::matrix_a, 16, 16, 8, wmma::precision::tf32, wmma::row_major> a0, a1;
            wmma::fragment<wmma::matrix_b, 16, 16, 8, wmma::precision::tf32, wmma::row_major> bf[4];
            wmma::load_matrix_sync(a0, &A[wm * ASTRIDE + kk * 8], ASTRIDE);
            wmma::load_matrix_sync(a1, &A[(wm + 16) * ASTRIDE + kk * 8], ASTRIDE);
#pragma unroll
            for (int j = 0; j < 4; j++)
                wmma::load_matrix_sync(bf[j], &B[kk * 8 * BSTRIDE + wn + j * 16], BSTRIDE);
#pragma unroll
            for (int j = 0; j < 4; j++) {
                wmma::mma_sync(acc[0][j], a0, bf[j], acc[0][j]);
                wmma::mma_sync(acc[1][j], a1, bf[j], acc[1][j]);
            }
        }

        if (t + 2 < 64) {
            load_tile(sm, X, W0, m0, n0, t + 2, (t + 2) % 3);
            cp_commit();
        }
    }
    __syncthreads();

    // ---- epilogue: Hs = tf32(elu(acc + b0)); partial B32 = Hs @ W1chunk ----
    float* Hs  = sm + HDRF;            // 128 x 132
    float* W1s = sm + HDRF + 16896;    // 128 x 36  (k-major [k][n])

#pragma unroll
    for (int i = 0; i < 2; i++)
#pragma unroll
        for (int j = 0; j < 4; j++)
            wmma::store_matrix_sync(&Hs[(wm + i * 16) * BSTRIDE + wn + j * 16],
                                    acc[i][j], BSTRIDE, wmma::mem_row_major);
    // stage W1 chunk (tf32-rounded)
    for (int i = tid; i < 128 * 32; i += 256) {
        int r = i >> 5, c = i & 31;
        W1s[r * ASTRIDE + c] = rnd_tf32(W1[(size_t)(n0 + r) * 32 + c]);
    }
    __syncthreads();

    for (int i = tid; i < 128 * 128; i += 256) {
        int r = i >> 7, c = i & 127;
        float v = Hs[r * BSTRIDE + c] + sm[c];
        Hs[r * BSTRIDE + c] = rnd_tf32(eluf(v));
    }
    __syncthreads();

    {
        int r0 = wid * 16;
        wmma::fragment<wmma::accumulator, 16, 16, 8, float> oacc[2];
        wmma::fill_fragment(oacc[0], 0.f);
        wmma::fill_fragment(oacc[1], 0.f);
#pragma unroll
        for (int kk = 0; kk < 16; kk++) {
            wmma::fragment<wmma::matrix_a, 16, 16, 8, wmma::precision::tf32, wmma::row_major> af;
            wmma::fragment<wmma::matrix_b, 16, 16, 8, wmma::precision::tf32, wmma::row_major> bf0, bf1;
            wmma::load_matrix_sync(af, &Hs[r0 * BSTRIDE + kk * 8], BSTRIDE);
            wmma::load_matrix_sync(bf0, &W1s[kk * 8 * ASTRIDE], ASTRIDE);
            wmma::load_matrix_sync(bf1, &W1s[kk * 8 * ASTRIDE + 16], ASTRIDE);
            wmma::mma_sync(oacc[0], af, bf0, oacc[0]);
            wmma::mma_sync(oacc[1], af, bf1, oacc[1]);
        }
        float* dst = g_part + (size_t)p * MROWS * 32 + (size_t)(m0 + r0) * 32;
        wmma::store_matrix_sync(dst, oacc[0], 32, wmma::mem_row_major);
        wmma::store_matrix_sync(dst + 16, oacc[1], 32, wmma::mem_row_major);
    }
}

// ---------------------------------------------------------------------------
// COMBINE: B32[r,:] = sum_p part[p][r,:] + b1 + elu(rd-MLP(ray_diff[r]))
// ---------------------------------------------------------------------------
__global__ void __launch_bounds__(256) combine_kernel(
    const float* __restrict__ b1, const float* __restrict__ rdiff,
    const float* __restrict__ rd0w, const float* __restrict__ rd0b,
    const float* __restrict__ rd1w, const float* __restrict__ rd1b)
{
    const int tid = threadIdx.x, wid = tid >> 5, lane = tid & 31;
    size_t r = (size_t)blockIdx.x * 8 + wid;

    const float* rp = rdiff + r * 4;
    float rv = (lane < 4) ? rp[lane] : 0.f;
    float r0 = __shfl_sync(0xffffffffu, rv, 0), r1 = __shfl_sync(0xffffffffu, rv, 1);
    float r2 = __shfl_sync(0xffffffffu, rv, 2), r3 = __shfl_sync(0xffffffffu, rv, 3);
    float h = 0.f;
    if (lane < 16) {
        h = rd0b[lane] + r0 * rd0w[lane] + r1 * rd0w[16 + lane]
                       + r2 * rd0w[32 + lane] + r3 * rd0w[48 + lane];
        h = eluf(h);
    }
    float d = rd1b[lane];
#pragma unroll
    for (int k = 0; k < 16; k++)
        d += __shfl_sync(0xffffffffu, h, k) * rd1w[k * 32 + lane];
    d = eluf(d);

    float s = b1[lane] + d;
#pragma unroll
    for (int p = 0; p < 4; p++)
        s += g_part[(size_t)p * MROWS * 32 + r * 32 + lane];
    g_B32[r * 32 + lane] = s;
}

// ---------------------------------------------------------------------------
// STAGE2: everything after if1 — warp per point, 8 points/block.
// bf0's globalfeat half hoisted out of the view loop (view-independent).
// ---------------------------------------------------------------------------
struct WPtrs { const float* p[20]; };

#define WTOT   19432
#define WARPTMP 928

__global__ void __launch_bounds__(256) stage2_kernel(
    const float* __restrict__ tokG, const void* __restrict__ invG,
    WPtrs wp, float* __restrict__ out)
{
    extern __shared__ float sm[];
    const int tid = threadIdx.x, wid = tid >> 5, lane = tid & 31;

    const int cnt[20] = {128,8,8,1,11264,64,2048,32,1024,32,1056,33,1024,32,32,1,2080,32,512,16};
    const int off[20] = {0,128,136,144,145,11409,11473,13521,13553,14577,14609,15665,15698,16722,16754,16786,16787,18867,18899,19411};
    for (int s = 0; s < 20; s++) {
        const float* src = wp.p[s]; float* dst = sm + off[s];
        for (int i = tid; i < cnt[s]; i += 256) dst[i] = src[i];
    }
    __syncthreads();

    const float* nr0w = sm;          const float* nr0b = sm + 128;
    const float* nr1w = sm + 136;    const float* nr1b = sm + 144;
    const float* bf0w = sm + 145;    const float* bf0b = sm + 11409;
    const float* bf1w = sm + 11473;  const float* bf1b = sm + 13521;
    const float* vf0w = sm + 13553;  const float* vf0b = sm + 14577;
    const float* vf1w = sm + 14609;  const float* vf1b = sm + 15665;
    const float* v20w = sm + 15698;  const float* v20b = sm + 16722;
    const float* v21w = sm + 16754;  const float* v21b = sm + 16786;
    const float* gf0w = sm + 16787;  const float* gf0b = sm + 18867;
    const float* gf1w = sm + 18899;  const float* gf1b = sm + 19411;

    float* T = sm + WTOT + wid * WARPTMP;
    float* tokW = T;        float* bottW = T + 128;  float* xW  = T + 384;
    float* gfW  = T + 640;  float* h64W  = T + 768;  float* h33W = T + 832;
    float* wtW  = T + 872;  float* w0W   = T + 880;  float* mskW = T + 888;
    float* visW = T + 896;  float* w2W   = T + 904;

    int t = blockIdx.x * 8 + wid;

    // dtype-robust invalid_features read (uint8 vs 4-byte encodings)
    const unsigned char* bb = (const unsigned char*)invG;
    int u8f = 0;
    for (int i = lane; i < 256; i += 32) if ((i & 3) && bb[i] == 1) u8f = 1;
    u8f = (__ballot_sync(0xffffffffu, u8f) != 0);

    for (int i = lane; i < 128; i += 32) tokW[i]  = tokG[(size_t)t * 128 + i];
    for (int i = lane; i < 256; i += 32) bottW[i] = g_B32[(size_t)t * 256 + i];
    float mv = 0.f;
    if (lane < 8) {
        int idx = t * 8 + lane;
        bool inv = u8f ? (bb[idx] != 0)
                       : (((const unsigned int*)invG)[idx] != 0u);
        mv = inv ? 0.f : 1.f;
    }
    float msum = wrsum(mv);
    if (lane < 8) { mskW[lane] = mv; wtW[lane] = mv / (msum + 1e-8f); }
    __syncwarp();

    // nr: 16 -> 8 (elu) -> 1, sigmoid, * weight
    if (lane < 8) {
        float hh[8];
#pragma unroll
        for (int i = 0; i < 8; i++) hh[i] = nr0b[i];
#pragma unroll
        for (int k = 0; k < 16; k++) {
            float tv = tokW[lane * 16 + k];
#pragma unroll
            for (int i = 0; i < 8; i++) hh[i] += tv * nr0w[k * 8 + i];
        }
        float s = nr1b[0];
#pragma unroll
        for (int i = 0; i < 8; i++) s += eluf(hh[i]) * nr1w[i];
        w0W[lane] = sigm(s) * wtW[lane];
    }
    __syncwarp();

    // weighted mean/var of bott
    {
        float m0 = 0.f, m1 = 0.f;
#pragma unroll
        for (int v = 0; v < 8; v++) { float b = bottW[v * 32 + lane]; m0 += b * w0W[v]; m1 += b * wtW[v]; }
        float v0 = 0.f, v1 = 0.f;
#pragma unroll
        for (int v = 0; v < 8; v++) {
            float b = bottW[v * 32 + lane]; float d0 = b - m0, d1 = b - m1;
            v0 += w0W[v] * d0 * d0; v1 += wtW[v] * d1 * d1;
        }
        gfW[lane] = m0; gfW[32 + lane] = v0; gfW[64 + lane] = m1; gfW[96 + lane] = v1;
    }
    __syncwarp();

    // hoisted (view-independent) globalfeat half of bf0
    float gfc0 = bf0b[lane], gfc1 = bf0b[32 + lane];
#pragma unroll 8
    for (int k = 0; k < 128; k++) {
        float g = gfW[k];
        gfc0 += g * bf0w[k * 64 + lane];
        gfc1 += g * bf0w[k * 64 + 32 + lane];
    }

    for (int v = 0; v < 8; v++) {
        // bf0 per-view part: 48 inputs -> 64 (elu)
        {
            float a0 = gfc0, a1 = gfc1;
#pragma unroll
            for (int k = 0; k < 32; k++) {
                float b = bottW[v * 32 + k];
                a0 += b * bf0w[(128 + k) * 64 + lane];
                a1 += b * bf0w[(128 + k) * 64 + 32 + lane];
            }
#pragma unroll
            for (int k = 0; k < 16; k++) {
                float tv = tokW[v * 16 + k];
                a0 += tv * bf0w[(160 + k) * 64 + lane];
                a1 += tv * bf0w[(160 + k) * 64 + 32 + lane];
            }
            h64W[lane] = eluf(a0);
            h64W[32 + lane] = eluf(a1);
        }
        __syncwarp();
        // bf1: 64 -> 32 (elu)
        {
            float a = bf1b[lane];
#pragma unroll
            for (int k = 0; k < 64; k++) a += h64W[k] * bf1w[k * 32 + lane];
            xW[v * 32 + lane] = eluf(a);
        }
        __syncwarp();
        // vf on x*weight
        float wv = wtW[v];
        {
            float a = vf0b[lane];
#pragma unroll
            for (int k = 0; k < 32; k++) a += xW[v * 32 + k] * wv * vf0w[k * 32 + lane];
            h33W[lane] = eluf(a);
        }
        __syncwarp();
        float xres;
        {
            float a = vf1b[lane];
#pragma unroll
            for (int k = 0; k < 32; k++) a += h33W[k] * vf1w[k * 33 + lane];
            xres = eluf(a);
        }
        if (lane == 0) {
            float a = vf1b[32];
#pragma unroll
            for (int k = 0; k < 32; k++) a += h33W[k] * vf1w[k * 33 + 32];
            visW[v] = sigm(eluf(a)) * mskW[v];
        }
        __syncwarp();
        xW[v * 32 + lane] += xres;
        __syncwarp();
        // v2 on x*vis
        float vv = visW[v];
        {
            float a = v20b[lane];
#pragma unroll
            for (int k = 0; k < 32; k++) a += xW[v * 32 + k] * vv * v20w[k * 32 + lane];
            h33W[lane] = eluf(a);
        }
        __syncwarp();
        {
            float pr = h33W[lane] * v21w[lane];
            float s = wrsum(pr) + v21b[0];
            if (lane == 0) w2W[v] = sigm(s) * mskW[v];
        }
        __syncwarp();
    }

    {
        float vv = (lane < 8) ? w2W[lane] : 0.f;
        float s = wrsum(vv);
        if (lane < 8) w2W[lane] = vv / (s + 1e-8f);
    }
    __syncwarp();
    float wbar;
    {
        float vv = (lane < 8) ? w2W[lane] : 0.f;
        wbar = wrsum(vv) * 0.125f;
    }
    {
        float m = 0.f;
#pragma unroll
        for (int v = 0; v < 8; v++) m += xW[v * 32 + lane] * w2W[v];
        float va = 0.f;
#pragma unroll
        for (int v = 0; v < 8; v++) { float dd = xW[v * 32 + lane] - m; va += w2W[v] * dd * dd; }
        gfW[lane] = m; gfW[32 + lane] = va;
        if (lane == 0) gfW[64] = wbar;
    }
    __syncwarp();
    {
        float a = gf0b[lane];
#pragma unroll
        for (int k = 0; k < 65; k++) a += gfW[k] * gf0w[k * 32 + lane];
        h33W[lane] = eluf(a);
    }
    __syncwarp();
    if (lane < 16) {
        float a = gf1b[lane];
#pragma unroll
        for (int k = 0; k < 32; k++) a += h33W[k] * gf1w[k * 16 + lane];
        out[(size_t)t * 16 + lane] = eluf(a);
    }
}

// ---------------------------------------------------------------------------
extern "C" void kernel_launch(void* const* d_in, const int* in_sizes, int n_in,
                              void* d_out, int out_size)
{
    const float* tok   = (const float*)d_in[0];
    const float* bott  = (const float*)d_in[1];
    const float* rdiff = (const float*)d_in[2];
    const void*  inval = (const void*)d_in[3];
    const float* rd0w = (const float*)d_in[4];  const float* rd0b = (const float*)d_in[5];
    const float* rd1w = (const float*)d_in[6];  const float* rd1b = (const float*)d_in[7];
    const float* if0w = (const float*)d_in[8];  const float* if0b = (const float*)d_in[9];
    const float* if1w = (const float*)d_in[10]; const float* if1b = (const float*)d_in[11];
    float* out = (float*)d_out;

    WPtrs wp;
    for (int i = 0; i < 20; i++) wp.p[i] = (const float*)d_in[12 + i];

    const int stage2_smem = (WTOT + 8 * WARPTMP) * 4;
    cudaFuncSetAttribute(gemm1_kernel, cudaFuncAttributeMaxDynamicSharedMemorySize, SMEM_G1);
    cudaFuncSetAttribute(stage2_kernel, cudaFuncAttributeMaxDynamicSharedMemorySize, stage2_smem);

    gemm1_kernel<<<dim3(4, 1024), 256, SMEM_G1>>>(bott, if0w, if0b, if1w);
    combine_kernel<<<MROWS / 8, 256>>>(if1b, rdiff, rd0w, rd0b, rd1w, rd1b);
    stage2_kernel<<<TOTPTS / 8, 256, stage2_smem>>>(tok, inval, wp, out);
}